// round 3
// baseline (speedup 1.0000x reference)
#include <cuda_runtime.h>
#include <cstdint>

#define BATCHN 8
#define SEQN   4096
#define NPOS   (BATCHN*SEQN)
#define VOCABN 257
#define QD     256
#define DEPTHN 6
#define BSV    (NPOS*VOCABN)

typedef unsigned long long ull;
typedef ulonglong2 ull2;

// ---------------- scratch (device globals; no allocations) ----------------
__device__ ull2  g_wL[DEPTHN*QD*2*128];   // [d][i][plane][o2] plane0=(wr01,wi01) plane1=(wj01,wk01) (6.3 MB)
__device__ float4 g_wHp[256*256];         // [k4][j<256] = w_head[j][4k4..4k4+3]  (1.05 MB)
__device__ float g_wH256[1024];           // w_head[256][k]
__device__ float g_qA[VOCABN*QD*4];       // q table ping (1.05 MB)
__device__ float g_qB[VOCABN*QD*4];       // q table pong
__device__ float g_logits[VOCABN*VOCABN]; // per-token logits (264 KB)
__device__ float g_L[VOCABN];             // per-token mean |q_r|
__device__ float g_part[64];              // loss partials

// ---------------- packed f32x2 helpers ----------------
__device__ __forceinline__ ull pack2f(float a, float b) {
    ull r;
    asm("mov.b64 %0, {%1, %2};" : "=l"(r) : "r"(__float_as_uint(a)), "r"(__float_as_uint(b)));
    return r;
}
__device__ __forceinline__ ull dup2f(float a) { return pack2f(a, a); }
__device__ __forceinline__ void fma2(ull& d, ull a, ull b) {
    asm("fma.rn.f32x2 %0, %1, %2, %0;" : "+l"(d) : "l"(a), "l"(b));
}
__device__ __forceinline__ ull add2(ull a, ull b) {
    ull d;
    asm("add.rn.f32x2 %0, %1, %2;" : "=l"(d) : "l"(a), "l"(b));
    return d;
}
__device__ __forceinline__ float2 unpack2(ull v) {
    unsigned int lo, hi;
    asm("mov.b64 {%0, %1}, %2;" : "=r"(lo), "=r"(hi) : "l"(v));
    return make_float2(__uint_as_float(lo), __uint_as_float(hi));
}
#define NEG2 0x8000000080000000ULL

__device__ __forceinline__ uint32_t smem_u32(const void* p) {
    uint32_t a;
    asm("{ .reg .u64 t; cvta.to.shared.u64 t, %1; cvt.u32.u64 %0, t; }" : "=r"(a) : "l"(p));
    return a;
}
__device__ __forceinline__ ull2 lds128(uint32_t a) {
    ull2 r;
    asm volatile("ld.shared.v2.u64 {%0, %1}, [%2];" : "=l"(r.x), "=l"(r.y) : "r"(a));
    return r;
}

#define MB_INIT(a, c) asm volatile("mbarrier.init.shared.b64 [%0], %1;" :: "r"(a), "r"(c) : "memory")
#define MB_EXPECT(a, b) asm volatile("mbarrier.arrive.expect_tx.shared.b64 _, [%0], %1;" :: "r"(a), "r"(b) : "memory")
#define MB_ARRIVE(a) asm volatile("mbarrier.arrive.shared.b64 _, [%0];" :: "r"(a) : "memory")
#define BULK_G2S(dst, src, bytes, mbar) \
    asm volatile("cp.async.bulk.shared::cluster.global.mbarrier::complete_tx::bytes [%0], [%1], %2, [%3];" \
                 :: "r"(dst), "l"(src), "r"(bytes), "r"(mbar) : "memory")
#define MB_WAITP(mbar, ph) do { \
    asm volatile("{\n\t.reg .pred P1;\n\tWL_%=:\n\t" \
        "mbarrier.try_wait.parity.acquire.cta.shared::cta.b64 P1, [%0], %1, 0x989680;\n\t" \
        "@P1 bra.uni WD_%=;\n\tbra.uni WL_%=;\n\tWD_%=:\n\t}" \
        :: "r"(mbar), "r"(ph) : "memory"); \
} while (0)

// ---------------- K0a: layer-weight repack to (o-pair, plane) layout ----------------
// grid = 6 d * 8 it(32 i) * 4 ot(64 o) = 192 blocks of 256 threads
__global__ void k_prep_layers(const float* __restrict__ wl) {
    __shared__ float t4[4][64][33];
    int b = blockIdx.x;
    int d = b / 32, r = b % 32;
    int it = r >> 2, ot = r & 3;
    int tid = threadIdx.x;
    int lane = tid & 31, row8 = tid >> 5;
#pragma unroll
    for (int c = 0; c < 4; c++)
#pragma unroll
        for (int rr = 0; rr < 8; rr++) {
            int ol = row8 + rr * 8;
            t4[c][ol][lane] =
                wl[(((size_t)d * 4 + c) * QD + ot * 64 + ol) * QD + it * 32 + lane];
        }
    __syncthreads();
    int o2l = lane, il8 = row8;
#pragma unroll
    for (int rr = 0; rr < 4; rr++) {
        int il = il8 + rr * 8;
        int i = it * 32 + il;
        int o2 = ot * 32 + o2l;
        ull wr = pack2f(t4[0][2 * o2l][il], t4[0][2 * o2l + 1][il]);
        ull wi = pack2f(t4[1][2 * o2l][il], t4[1][2 * o2l + 1][il]);
        ull wj = pack2f(t4[2][2 * o2l][il], t4[2][2 * o2l + 1][il]);
        ull wk = pack2f(t4[3][2 * o2l][il], t4[3][2 * o2l + 1][il]);
        ull2 p0; p0.x = wr; p0.y = wi;
        ull2 p1; p1.x = wj; p1.y = wk;
        g_wL[(((size_t)d * QD + i) * 2 + 0) * 128 + o2] = p0;
        g_wL[(((size_t)d * QD + i) * 2 + 1) * 128 + o2] = p1;
    }
}

// ---------------- K0b: head-weight retile [j][k] -> [k4][j<256], plus j=256 row ----------------
__global__ void k_prep_head(const float* __restrict__ wh) {
    int b = blockIdx.x;
    int tid = threadIdx.x;
    if (b == 64) {
        for (int k = tid; k < 1024; k += 256) g_wH256[k] = wh[(size_t)256 * 1024 + k];
        return;
    }
    int jt = b >> 3, kt = b & 7;
    __shared__ float4 tile[32][33];
    int col = tid & 31, row8 = tid >> 5;
#pragma unroll
    for (int s = 0; s < 4; s++) {
        int jj = row8 + s * 8;
        int j = jt * 32 + jj, k4 = kt * 32 + col;
        tile[jj][col] = *(const float4*)(wh + (size_t)j * 1024 + k4 * 4);
    }
    __syncthreads();
#pragma unroll
    for (int s = 0; s < 4; s++) {
        int kk = row8 + s * 8;
        int k4 = kt * 32 + kk, j = jt * 32 + col;
        g_wHp[(size_t)k4 * 256 + j] = tile[col][kk];
    }
}

// ---------------- K1: expansion stages (cq 1 -> 256) ----------------
__global__ void k_expand(const float* __restrict__ emb,
                         const float* __restrict__ e0, const float* __restrict__ e1,
                         const float* __restrict__ e2, const float* __restrict__ e3,
                         const float* __restrict__ e4, const float* __restrict__ e5,
                         const float* __restrict__ e6, const float* __restrict__ e7) {
    __shared__ float4 bufA[QD];
    __shared__ float4 bufB[QD];
    int v = blockIdx.x, tid = threadIdx.x;
    if (tid == 0)
        bufA[0] = make_float4(emb[v * 4 + 0], emb[v * 4 + 1], emb[v * 4 + 2], emb[v * 4 + 3]);
    __syncthreads();
    const float* ws[8] = {e0, e1, e2, e3, e4, e5, e6, e7};
    float4* cur = bufA;
    float4* nxt = bufB;
    for (int s = 0; s < 8; s++) {
        int cq = 1 << s;
        if (tid < cq) {
            const float* W = ws[s];
            int cq2 = cq * cq;
            float dr = 0.f, di = 0.f, dj = 0.f, dk = 0.f;
            for (int i = 0; i < cq; i++) {
                float4 q = cur[i];
                float wr = W[tid * cq + i];
                float wi = W[cq2 + tid * cq + i];
                float wj = W[2 * cq2 + tid * cq + i];
                float wk = W[3 * cq2 + tid * cq + i];
                dr += wr * q.x - wi * q.y - wj * q.z - wk * q.w;
                di += wi * q.x + wr * q.y + wk * q.z - wj * q.w;
                dj += wj * q.x - wk * q.y + wr * q.z + wi * q.w;
                dk += wk * q.x + wj * q.y - wi * q.z + wr * q.w;
            }
            dr = tanhf(dr); di = tanhf(di); dj = tanhf(dj); dk = tanhf(dk);
            float4 q = cur[tid];
            nxt[tid]      = make_float4(q.x + dr, q.y + di, q.z + dj, q.w + dk);
            nxt[tid + cq] = make_float4(q.x - dr, q.y - di, q.z - dj, q.w - dk);
        }
        __syncthreads();
        float4* t = cur; cur = nxt; nxt = t;
    }
    float4* o4 = (float4*)(g_qA + (size_t)v * QD * 4);
    o4[tid]       = cur[tid];
    o4[tid + 128] = cur[tid + 128];
}

// ---------------- K2: quaternion layer; bulk-copy staged, o-pair packed ----------------
#define LCHUNK 65536
#define LBUF_OFF 0
#define LQD_OFF  131072
#define LMB_OFF  147456
#define LSMEM    147520

__global__ void __launch_bounds__(512, 1) k_layer(int d, int flip) {
    extern __shared__ char sm[];
    uint32_t sb = smem_u32(sm);
    const float* __restrict__ src = flip ? g_qB : g_qA;
    float* __restrict__ dst       = flip ? g_qA : g_qB;
    int tid = threadIdx.x;
    int o2 = tid & 127, p = tid >> 7;
    int t0 = blockIdx.x * 2;
    int t1 = t0 + 1; if (t1 > 256) t1 = 256;
    uint32_t full0 = sb + LMB_OFF, full1 = full0 + 8, emp0 = full0 + 16, emp1 = full0 + 24;

    // q lane-duplicated into smem: tid -> (token half, i)
    {
        int th = tid >> 8;
        int i = tid & 255;
        int t = th ? t1 : t0;
        float4 g = ((const float4*)(src + (size_t)t * 1024))[i];
        ull* q = (ull*)(sm + LQD_OFF) + ((size_t)th * 256 + i) * 4;
        q[0] = dup2f(g.x); q[1] = dup2f(g.y); q[2] = dup2f(g.z); q[3] = dup2f(g.w);
    }
    if (tid == 0) {
        MB_INIT(full0, 1); MB_INIT(full1, 1);
        MB_INIT(emp0, 512); MB_INIT(emp1, 512);
    }
    __syncthreads();

    const char* wsrc = (const char*)g_wL + ((size_t)d << 20);
    if (tid == 0) {
        MB_EXPECT(full0, LCHUNK);
        BULK_G2S(sb + LBUF_OFF, wsrc, LCHUNK, full0);
        MB_EXPECT(full1, LCHUNK);
        BULK_G2S(sb + LBUF_OFF + LCHUNK, wsrc + LCHUNK, LCHUNK, full1);
    }

    ull P0[16], P1[16];
#pragma unroll
    for (int n = 0; n < 16; n++) { P0[n] = 0ull; P1[n] = 0ull; }
    int fp0 = 0, fp1 = 0, ep0 = 0, ep1 = 0;
    const uint32_t qb0 = sb + LQD_OFF;
    const uint32_t qb1 = qb0 + 256 * 32;

    for (int s = 0; s < 16; s++) {
        int b = s & 1;
        uint32_t fullb = b ? full1 : full0;
        if (b) { MB_WAITP(fullb, fp1); } else { MB_WAITP(fullb, fp0); }
        uint32_t wbase = sb + LBUF_OFF + b * LCHUNK + (p * 4) * 4096 + o2 * 16;
        int ibase = s * 16 + p * 4;
#pragma unroll
        for (int n = 0; n < 4; n++) {
            ull2 w0 = lds128(wbase + n * 4096);          // wr01, wi01
            ull2 w1 = lds128(wbase + n * 4096 + 2048);   // wj01, wk01
            uint32_t qa0 = qb0 + (ibase + n) * 32;
            uint32_t qa1 = qb1 + (ibase + n) * 32;
            ull2 q0a = lds128(qa0), q0b = lds128(qa0 + 16);
            ull2 q1a = lds128(qa1), q1b = lds128(qa1 + 16);
            fma2(P0[0],  w0.x, q0a.x); fma2(P0[1],  w0.x, q0a.y); fma2(P0[2],  w0.x, q0b.x); fma2(P0[3],  w0.x, q0b.y);
            fma2(P0[4],  w0.y, q0a.x); fma2(P0[5],  w0.y, q0a.y); fma2(P0[6],  w0.y, q0b.x); fma2(P0[7],  w0.y, q0b.y);
            fma2(P0[8],  w1.x, q0a.x); fma2(P0[9],  w1.x, q0a.y); fma2(P0[10], w1.x, q0b.x); fma2(P0[11], w1.x, q0b.y);
            fma2(P0[12], w1.y, q0a.x); fma2(P0[13], w1.y, q0a.y); fma2(P0[14], w1.y, q0b.x); fma2(P0[15], w1.y, q0b.y);
            fma2(P1[0],  w0.x, q1a.x); fma2(P1[1],  w0.x, q1a.y); fma2(P1[2],  w0.x, q1b.x); fma2(P1[3],  w0.x, q1b.y);
            fma2(P1[4],  w0.y, q1a.x); fma2(P1[5],  w0.y, q1a.y); fma2(P1[6],  w0.y, q1b.x); fma2(P1[7],  w0.y, q1b.y);
            fma2(P1[8],  w1.x, q1a.x); fma2(P1[9],  w1.x, q1a.y); fma2(P1[10], w1.x, q1b.x); fma2(P1[11], w1.x, q1b.y);
            fma2(P1[12], w1.y, q1a.x); fma2(P1[13], w1.y, q1a.y); fma2(P1[14], w1.y, q1b.x); fma2(P1[15], w1.y, q1b.y);
        }
        if (b) fp1 ^= 1; else fp0 ^= 1;
        if (s < 14) {
            MB_ARRIVE(b ? emp1 : emp0);
            if (tid == 0) {
                MB_EXPECT(fullb, LCHUNK);
                if (b) { MB_WAITP(emp1, ep1); ep1 ^= 1; }
                else   { MB_WAITP(emp0, ep0); ep0 ^= 1; }
                BULK_G2S(sb + LBUF_OFF + b * LCHUNK, wsrc + (size_t)(s + 2) * LCHUNK, LCHUNK, fullb);
            }
        }
    }

    __syncthreads();
    ull* red = (ull*)sm;  // reuse weight buffers (96 KB)
    if (p) {
        int base = (p - 1) * 32 * 128;
#pragma unroll
        for (int n = 0; n < 16; n++) {
            red[base + n * 128 + o2]        = P0[n];
            red[base + (16 + n) * 128 + o2] = P1[n];
        }
    }
    __syncthreads();
    if (p == 0) {
#pragma unroll
        for (int pp = 0; pp < 3; pp++)
#pragma unroll
            for (int n = 0; n < 16; n++) {
                P0[n] = add2(P0[n], red[(pp * 32 + n) * 128 + o2]);
                P1[n] = add2(P1[n], red[(pp * 32 + 16 + n) * 128 + o2]);
            }
#pragma unroll
        for (int t = 0; t < 2; t++) {
            ull* P = t ? P1 : P0;
            ull dr = add2(add2(P[0],  P[5]  ^ NEG2), add2(P[10] ^ NEG2, P[15] ^ NEG2));
            ull di = add2(add2(P[4],  P[1]),         add2(P[14],        P[11] ^ NEG2));
            ull dj = add2(add2(P[8],  P[13] ^ NEG2), add2(P[2],         P[7]));
            ull dk = add2(add2(P[12], P[9]),         add2(P[6]  ^ NEG2, P[3]));
            float2 R = unpack2(dr), I = unpack2(di), J = unpack2(dj), K = unpack2(dk);
            int tt = t ? t1 : t0;
            float4* drow = (float4*)(dst + (size_t)tt * 1024);
            float n0 = sqrtf(R.x * R.x + I.x * I.x + J.x * J.x + K.x * K.x);
            float v0 = 1.0f / (n0 + 1e-8f);
            drow[2 * o2] = make_float4(R.x * v0, I.x * v0, J.x * v0, K.x * v0);
            float n1 = sqrtf(R.y * R.y + I.y * I.y + J.y * J.y + K.y * K.y);
            float v1 = 1.0f / (n1 + 1e-8f);
            drow[2 * o2 + 1] = make_float4(R.y * v1, I.y * v1, J.y * v1, K.y * v1);
        }
    }
}

// ---------------- K3: per-token stability mean |q_r| ----------------
__global__ void k_L() {
    __shared__ float red[256];
    int v = blockIdx.x, tid = threadIdx.x;
    red[tid] = fabsf(g_qA[((size_t)v * QD + tid) * 4]);
    __syncthreads();
    for (int s = 128; s > 0; s >>= 1) {
        if (tid < s) red[tid] += red[tid + s];
        __syncthreads();
    }
    if (tid == 0) g_L[v] = red[0] * (1.0f / QD);
}

// ---------------- K4: head GEMM; 4 tokens/block, bulk staged ----------------
#define HBUF_OFF 0
#define HQH_OFF  131072
#define HMB_OFF  147456
#define HR2_OFF  147488
#define HSMEM    147744

__global__ void __launch_bounds__(512, 1) k_head() {
    extern __shared__ char sm[];
    uint32_t sb = smem_u32(sm);
    int tid = threadIdx.x;
    int j = tid & 255, p = tid >> 8;
    int bid = blockIdx.x;
    int tok[4];
#pragma unroll
    for (int n = 0; n < 4; n++) { tok[n] = bid * 4 + n; if (tok[n] > 256) tok[n] = 256; }
    uint32_t full0 = sb + HMB_OFF, full1 = full0 + 8, emp0 = full0 + 16, emp1 = full0 + 24;

    // stage q rows into smem (float4 per (t,k4))
    {
        float4* qh = (float4*)(sm + HQH_OFF);
#pragma unroll
        for (int r = 0; r < 2; r++) {
            int idx = tid + r * 512;
            int t = idx >> 8, k4 = idx & 255;
            qh[idx] = ((const float4*)(g_qA + (size_t)tok[t] * 1024))[k4];
        }
    }
    if (tid == 0) {
        MB_INIT(full0, 1); MB_INIT(full1, 1);
        MB_INIT(emp0, 512); MB_INIT(emp1, 512);
    }
    __syncthreads();

    const char* wsrc = (const char*)g_wHp;
    if (tid == 0) {
        MB_EXPECT(full0, LCHUNK);
        BULK_G2S(sb + HBUF_OFF, wsrc, LCHUNK, full0);
        MB_EXPECT(full1, LCHUNK);
        BULK_G2S(sb + HBUF_OFF + LCHUNK, wsrc + LCHUNK, LCHUNK, full1);
    }

    ull a[4];
#pragma unroll
    for (int t = 0; t < 4; t++) a[t] = 0ull;
    int fp0 = 0, fp1 = 0, ep0 = 0, ep1 = 0;
    const uint32_t qhb = sb + HQH_OFF;

    for (int s = 0; s < 16; s++) {
        int b = s & 1;
        uint32_t fullb = b ? full1 : full0;
        if (b) { MB_WAITP(fullb, fp1); } else { MB_WAITP(fullb, fp0); }
        uint32_t wbase = sb + HBUF_OFF + b * LCHUNK + (p * 8) * 4096 + j * 16;
        int kbase = s * 16 + p * 8;
#pragma unroll
        for (int n = 0; n < 8; n++) {
            ull2 w = lds128(wbase + n * 4096);
            uint32_t qa = qhb + (kbase + n) * 16;
            ull2 q0 = lds128(qa);
            ull2 q1 = lds128(qa + 256 * 16);
            ull2 q2 = lds128(qa + 512 * 16);
            ull2 q3 = lds128(qa + 768 * 16);
            fma2(a[0], w.x, q0.x); fma2(a[0], w.y, q0.y);
            fma2(a[1], w.x, q1.x); fma2(a[1], w.y, q1.y);
            fma2(a[2], w.x, q2.x); fma2(a[2], w.y, q2.y);
            fma2(a[3], w.x, q3.x); fma2(a[3], w.y, q3.y);
        }
        if (b) fp1 ^= 1; else fp0 ^= 1;
        if (s < 14) {
            MB_ARRIVE(b ? emp1 : emp0);
            if (tid == 0) {
                MB_EXPECT(fullb, LCHUNK);
                if (b) { MB_WAITP(emp1, ep1); ep1 ^= 1; }
                else   { MB_WAITP(emp0, ep0); ep0 ^= 1; }
                BULK_G2S(sb + HBUF_OFF + b * LCHUNK, wsrc + (size_t)(s + 2) * LCHUNK, LCHUNK, fullb);
            }
        }
    }

    __syncthreads();
    ull* red = (ull*)sm;  // reuse buffer: 4 tokens x 256 j
    if (p == 1) {
#pragma unroll
        for (int t = 0; t < 4; t++) red[t * 256 + j] = a[t];
    }
    // j == 256 column: k = 2*tid, 2*tid+1
    {
        const float* qf = (const float*)(sm + HQH_OFF);
        float* r2 = (float*)(sm + HR2_OFF);
        int k0 = tid * 2;
        float w0 = g_wH256[k0], w1 = g_wH256[k0 + 1];
        float sv[4];
#pragma unroll
        for (int t = 0; t < 4; t++)
            sv[t] = w0 * qf[t * 1024 + k0] + w1 * qf[t * 1024 + k0 + 1];
#pragma unroll
        for (int off = 16; off; off >>= 1)
#pragma unroll
            for (int t = 0; t < 4; t++)
                sv[t] += __shfl_down_sync(0xFFFFFFFFu, sv[t], off);
        if ((tid & 31) == 0) {
            int w = tid >> 5;
#pragma unroll
            for (int t = 0; t < 4; t++) r2[w * 4 + t] = sv[t];
        }
    }
    __syncthreads();
    if (p == 0) {
#pragma unroll
        for (int t = 0; t < 4; t++) {
            ull v = add2(a[t], red[t * 256 + j]);
            float2 f = unpack2(v);
            g_logits[(size_t)tok[t] * VOCABN + j] = f.x + f.y;
        }
    }
    if (tid == 0) {
        const float* r2 = (const float*)(sm + HR2_OFF);
        float sv[4] = {0.f, 0.f, 0.f, 0.f};
#pragma unroll
        for (int w = 0; w < 16; w++)
#pragma unroll
            for (int t = 0; t < 4; t++) sv[t] += r2[w * 4 + t];
#pragma unroll
        for (int t = 0; t < 4; t++)
            g_logits[(size_t)tok[t] * VOCABN + 256] = sv[t];
    }
}

// ---------------- K5: gather logits to output ----------------
__global__ void k_gather(const int* __restrict__ x, float* __restrict__ out) {
    int warp = threadIdx.x >> 5, lane = threadIdx.x & 31;
    int pp = blockIdx.x * 8 + warp;
    int tokv = x[pp];
    const float* row = g_logits + (size_t)tokv * VOCABN;
    float* orow = out + (size_t)pp * VOCABN;
    for (int v = lane; v < VOCABN; v += 32)
        orow[v] = row[v];
}

// ---------------- K6: stability loss (2-stage) ----------------
__global__ void k_loss1(const int* __restrict__ x) {
    __shared__ float red[256];
    int tid = threadIdx.x;
    int base = blockIdx.x * 512;
    red[tid] = g_L[x[base + tid]] + g_L[x[base + 256 + tid]];
    __syncthreads();
    for (int k = 128; k > 0; k >>= 1) {
        if (tid < k) red[tid] += red[tid + k];
        __syncthreads();
    }
    if (tid == 0) g_part[blockIdx.x] = red[0];
}
__global__ void k_loss2(float* __restrict__ out, int out_size) {
    __shared__ float w2[2];
    int tid = threadIdx.x;
    float s = g_part[tid];
#pragma unroll
    for (int off = 16; off; off >>= 1)
        s += __shfl_down_sync(0xFFFFFFFFu, s, off);
    if ((tid & 31) == 0) w2[tid >> 5] = s;
    __syncthreads();
    if (tid == 0 && out_size > BSV)
        out[BSV] = (w2[0] + w2[1]) * (1.0f / NPOS);
}

// ---------------- launch ----------------
extern "C" void kernel_launch(void* const* d_in, const int* in_sizes, int n_in,
                              void* d_out, int out_size) {
    (void)in_sizes; (void)n_in;
    const int*   x   = (const int*)d_in[0];
    const float* emb = (const float*)d_in[1];
    const float* e0  = (const float*)d_in[2];
    const float* e1  = (const float*)d_in[3];
    const float* e2  = (const float*)d_in[4];
    const float* e3  = (const float*)d_in[5];
    const float* e4  = (const float*)d_in[6];
    const float* e5  = (const float*)d_in[7];
    const float* e6  = (const float*)d_in[8];
    const float* e7  = (const float*)d_in[9];
    const float* wl  = (const float*)d_in[10];
    const float* wh  = (const float*)d_in[11];
    float* out = (float*)d_out;

    cudaFuncSetAttribute(k_layer, cudaFuncAttributeMaxDynamicSharedMemorySize, LSMEM);
    cudaFuncSetAttribute(k_head,  cudaFuncAttributeMaxDynamicSharedMemorySize, HSMEM);

    k_prep_layers<<<192, 256>>>(wl);
    k_prep_head<<<65, 256>>>(wh);
    k_expand<<<VOCABN, 128>>>(emb, e0, e1, e2, e3, e4, e5, e6, e7);
    for (int d = 0; d < DEPTHN; d++)
        k_layer<<<(VOCABN + 1) / 2, 512, LSMEM>>>(d, d & 1);
    k_L<<<VOCABN, 256>>>();
    k_head<<<(VOCABN + 3) / 4, 512, HSMEM>>>();
    k_gather<<<NPOS / 8, 256>>>(x, out);
    k_loss1<<<64, 256>>>(x);
    k_loss2<<<1, 64>>>(out, out_size);
}

// round 4
// speedup vs baseline: 1.0978x; 1.0978x over previous
#include <cuda_runtime.h>
#include <cstdint>

#define BATCHN 8
#define SEQN   4096
#define NPOS   (BATCHN*SEQN)
#define VOCABN 257
#define QD     256
#define DEPTHN 6
#define BSV    (NPOS*VOCABN)

typedef unsigned long long ull;
typedef ulonglong2 ull2;

// ---------------- scratch (device globals; no allocations) ----------------
// layer weights: [(d*256+i)*128 + o2] * 2 + plane  (ull2 = 16B each; 32B per (i,o2))
//   plane0 = (wr[2o2],wr[2o2+1]) , (wi...) ; plane1 = (wj...),(wk...)
__device__ ull2   g_wL[DEPTHN*QD*128*2];   // 6.3 MB
__device__ float4 g_wH4[256*VOCABN];       // [k4][j] -> w_head[j][4k4..4k4+3] (1.05 MB)
__device__ float  g_qA[VOCABN*QD*4];       // q table ping (1.05 MB)
__device__ float  g_qB[VOCABN*QD*4];       // q table pong
__device__ float  g_logits[VOCABN*VOCABN]; // per-token logits (264 KB)
__device__ float  g_L[VOCABN];             // per-token mean |q_r|
__device__ float  g_part[64];              // loss partials

// ---------------- packed f32x2 helpers ----------------
__device__ __forceinline__ ull pack2f(float a, float b) {
    ull r;
    asm("mov.b64 %0, {%1, %2};" : "=l"(r) : "r"(__float_as_uint(a)), "r"(__float_as_uint(b)));
    return r;
}
__device__ __forceinline__ ull dup2f(float a) { return pack2f(a, a); }
__device__ __forceinline__ void fma2(ull& d, ull a, ull b) {
    asm("fma.rn.f32x2 %0, %1, %2, %0;" : "+l"(d) : "l"(a), "l"(b));
}
__device__ __forceinline__ ull add2(ull a, ull b) {
    ull d;
    asm("add.rn.f32x2 %0, %1, %2;" : "=l"(d) : "l"(a), "l"(b));
    return d;
}
__device__ __forceinline__ float2 unpack2(ull v) {
    unsigned int lo, hi;
    asm("mov.b64 {%0, %1}, %2;" : "=r"(lo), "=r"(hi) : "l"(v));
    return make_float2(__uint_as_float(lo), __uint_as_float(hi));
}
#define NEG2 0x8000000080000000ULL

// ---------------- K0a: layer-weight repack to interleaved (o-pair, plane) layout ----------------
// grid = 6 d * 8 it(32 i) * 4 ot(64 o) = 192 blocks of 256 threads
__global__ void k_prep_layers(const float* __restrict__ wl) {
    __shared__ float t4[4][64][33];
    int b = blockIdx.x;
    int d = b / 32, r = b % 32;
    int it = r >> 2, ot = r & 3;
    int tid = threadIdx.x;
    int lane = tid & 31, row8 = tid >> 5;
#pragma unroll
    for (int c = 0; c < 4; c++)
#pragma unroll
        for (int rr = 0; rr < 8; rr++) {
            int ol = row8 + rr * 8;
            t4[c][ol][lane] =
                wl[(((size_t)d * 4 + c) * QD + ot * 64 + ol) * QD + it * 32 + lane];
        }
    __syncthreads();
    int o2l = lane, il8 = row8;
#pragma unroll
    for (int rr = 0; rr < 4; rr++) {
        int il = il8 + rr * 8;
        int i = it * 32 + il;
        int o2 = ot * 32 + o2l;
        ull wr = pack2f(t4[0][2 * o2l][il], t4[0][2 * o2l + 1][il]);
        ull wi = pack2f(t4[1][2 * o2l][il], t4[1][2 * o2l + 1][il]);
        ull wj = pack2f(t4[2][2 * o2l][il], t4[2][2 * o2l + 1][il]);
        ull wk = pack2f(t4[3][2 * o2l][il], t4[3][2 * o2l + 1][il]);
        ull2 p0; p0.x = wr; p0.y = wi;
        ull2 p1; p1.x = wj; p1.y = wk;
        size_t base = (((size_t)d * QD + i) * 128 + o2) * 2;
        g_wL[base + 0] = p0;
        g_wL[base + 1] = p1;
    }
}

// ---------------- K0b: head-weight retile [j][k] -> [k4][j] ----------------
__global__ void k_prep_head(const float* __restrict__ wh) {
    int b = blockIdx.x;
    int jt = b >> 3, kt = b & 7;
    __shared__ float4 tile[32][33];
    int tid = threadIdx.x;
    int col = tid & 31, row8 = tid >> 5;
#pragma unroll
    for (int s = 0; s < 4; s++) {
        int jj = row8 + s * 8;
        int j = jt * 32 + jj, k4 = kt * 32 + col;
        if (j < VOCABN)
            tile[jj][col] = *(const float4*)(wh + (size_t)j * 1024 + k4 * 4);
    }
    __syncthreads();
#pragma unroll
    for (int s = 0; s < 4; s++) {
        int kk = row8 + s * 8;
        int k4 = kt * 32 + kk, j = jt * 32 + col;
        if (j < VOCABN)
            g_wH4[(size_t)k4 * VOCABN + j] = tile[col][kk];
    }
}

// ---------------- K1: expansion stages (cq 1 -> 256) ----------------
__global__ void k_expand(const float* __restrict__ emb,
                         const float* __restrict__ e0, const float* __restrict__ e1,
                         const float* __restrict__ e2, const float* __restrict__ e3,
                         const float* __restrict__ e4, const float* __restrict__ e5,
                         const float* __restrict__ e6, const float* __restrict__ e7) {
    __shared__ float4 bufA[QD];
    __shared__ float4 bufB[QD];
    int v = blockIdx.x, tid = threadIdx.x;
    if (tid == 0)
        bufA[0] = make_float4(emb[v * 4 + 0], emb[v * 4 + 1], emb[v * 4 + 2], emb[v * 4 + 3]);
    __syncthreads();
    const float* ws[8] = {e0, e1, e2, e3, e4, e5, e6, e7};
    float4* cur = bufA;
    float4* nxt = bufB;
    for (int s = 0; s < 8; s++) {
        int cq = 1 << s;
        if (tid < cq) {
            const float* W = ws[s];
            int cq2 = cq * cq;
            float dr = 0.f, di = 0.f, dj = 0.f, dk = 0.f;
            for (int i = 0; i < cq; i++) {
                float4 q = cur[i];
                float wr = W[tid * cq + i];
                float wi = W[cq2 + tid * cq + i];
                float wj = W[2 * cq2 + tid * cq + i];
                float wk = W[3 * cq2 + tid * cq + i];
                dr += wr * q.x - wi * q.y - wj * q.z - wk * q.w;
                di += wi * q.x + wr * q.y + wk * q.z - wj * q.w;
                dj += wj * q.x - wk * q.y + wr * q.z + wi * q.w;
                dk += wk * q.x + wj * q.y - wi * q.z + wr * q.w;
            }
            dr = tanhf(dr); di = tanhf(di); dj = tanhf(dj); dk = tanhf(dk);
            float4 q = cur[tid];
            nxt[tid]      = make_float4(q.x + dr, q.y + di, q.z + dj, q.w + dk);
            nxt[tid + cq] = make_float4(q.x - dr, q.y - di, q.z - dj, q.w - dk);
        }
        __syncthreads();
        float4* t = cur; cur = nxt; nxt = t;
    }
    float4* o4 = (float4*)(g_qA + (size_t)v * QD * 4);
    o4[tid]       = cur[tid];
    o4[tid + 128] = cur[tid + 128];
}

// ---------------- K2: quaternion layer; o-pair packed, token-in-lane, 1024 thr ----------------
// thread: t = tid&1 (token), o2 = (tid>>1)&127 (output pair), p = tid>>8 (K-split/4)
__global__ void __launch_bounds__(1024, 1) k_layer(int d, int flip) {
    const float* __restrict__ src = flip ? g_qB : g_qA;
    float* __restrict__ dst       = flip ? g_qA : g_qB;
    __shared__ ull sq[2 * 256 * 4];   // [t][i][comp] lane-duplicated q (16 KB)
    __shared__ ull red[3 * 256 * 4];  // K-split partials post-combine (24 KB)
    int tid = threadIdx.x;
    int t = tid & 1, o2 = (tid >> 1) & 127, p = tid >> 8;
    int t0 = blockIdx.x * 2;
    int t1 = t0 + 1; if (t1 > 256) t1 = 256;

    if (tid < 512) {
        int tq = tid >> 8, i = tid & 255;
        int tok = tq ? t1 : t0;
        float4 g = ((const float4*)(src + (size_t)tok * 1024))[i];
        ull* qp = sq + ((size_t)tq * 256 + i) * 4;
        qp[0] = dup2f(g.x); qp[1] = dup2f(g.y); qp[2] = dup2f(g.z); qp[3] = dup2f(g.w);
    }
    __syncthreads();

    ull P[16];
#pragma unroll
    for (int n = 0; n < 16; n++) P[n] = 0ull;

    const ull2* wb = g_wL + (((size_t)d * QD + p * 64) * 128 + o2) * 2;
    const ull*  qb = sq + ((size_t)t * 256 + p * 64) * 4;
#pragma unroll 4
    for (int n = 0; n < 64; n++) {
        ull2 w0 = __ldg(wb + (size_t)n * 256);      // (wr01, wi01)
        ull2 w1 = __ldg(wb + (size_t)n * 256 + 1);  // (wj01, wk01)
        ull2 qa = *(const ull2*)(qb + 4 * n);       // (qr, qi) duplicated
        ull2 qc = *(const ull2*)(qb + 4 * n + 2);   // (qj, qk) duplicated
        fma2(P[0],  w0.x, qa.x); fma2(P[1],  w0.x, qa.y); fma2(P[2],  w0.x, qc.x); fma2(P[3],  w0.x, qc.y);
        fma2(P[4],  w0.y, qa.x); fma2(P[5],  w0.y, qa.y); fma2(P[6],  w0.y, qc.x); fma2(P[7],  w0.y, qc.y);
        fma2(P[8],  w1.x, qa.x); fma2(P[9],  w1.x, qa.y); fma2(P[10], w1.x, qc.x); fma2(P[11], w1.x, qc.y);
        fma2(P[12], w1.y, qa.x); fma2(P[13], w1.y, qa.y); fma2(P[14], w1.y, qc.x); fma2(P[15], w1.y, qc.y);
    }

    // Hamilton combine (packed over the o-pair)
    ull dr = add2(add2(P[0],  P[5]  ^ NEG2), add2(P[10] ^ NEG2, P[15] ^ NEG2));
    ull di = add2(add2(P[4],  P[1]),         add2(P[14],        P[11] ^ NEG2));
    ull dj = add2(add2(P[8],  P[13] ^ NEG2), add2(P[2],         P[7]));
    ull dk = add2(add2(P[12], P[9]),         add2(P[6]  ^ NEG2, P[3]));

    int slot = t * 128 + o2;  // 0..255
    if (p) {
        ull* r = red + ((size_t)(p - 1) * 256 + slot) * 4;
        r[0] = dr; r[1] = di; r[2] = dj; r[3] = dk;
    }
    __syncthreads();
    if (p == 0) {
#pragma unroll
        for (int pp = 0; pp < 3; pp++) {
            const ull* r = red + ((size_t)pp * 256 + slot) * 4;
            dr = add2(dr, r[0]); di = add2(di, r[1]); dj = add2(dj, r[2]); dk = add2(dk, r[3]);
        }
        float2 R = unpack2(dr), I = unpack2(di), J = unpack2(dj), K = unpack2(dk);
        int tok = t ? t1 : t0;
        float4* drow = (float4*)(dst + (size_t)tok * 1024);
        float n0 = sqrtf(R.x * R.x + I.x * I.x + J.x * J.x + K.x * K.x);
        float v0 = 1.0f / (n0 + 1e-8f);
        drow[2 * o2] = make_float4(R.x * v0, I.x * v0, J.x * v0, K.x * v0);
        float n1 = sqrtf(R.y * R.y + I.y * I.y + J.y * J.y + K.y * K.y);
        float v1 = 1.0f / (n1 + 1e-8f);
        drow[2 * o2 + 1] = make_float4(R.y * v1, I.y * v1, J.y * v1, K.y * v1);
    }
}

// ---------------- K3: per-token stability mean |q_r| ----------------
__global__ void k_L() {
    __shared__ float red[256];
    int v = blockIdx.x, tid = threadIdx.x;
    red[tid] = fabsf(g_qA[((size_t)v * QD + tid) * 4]);
    __syncthreads();
    for (int s = 128; s > 0; s >>= 1) {
        if (tid < s) red[tid] += red[tid + s];
        __syncthreads();
    }
    if (tid == 0) g_L[v] = red[0] * (1.0f / QD);
}

// ---------------- K4: head GEMM; 2 tokens/block, 1024 thr, 4-way K-split ----------------
__global__ void __launch_bounds__(1024, 1) k_head() {
    __shared__ ull hq[2][512];     // (q_k, q_{k+1}) pairs per token (8 KB)
    __shared__ ull redh[2][768];   // K-split partials (12 KB)
    __shared__ float redj[2][32];  // j=256 column partials
    int tid = threadIdx.x;
    int j = tid & 255, p = tid >> 8;
    int t0 = blockIdx.x * 2;
    int t1 = t0 + 1; if (t1 > VOCABN - 1) t1 = VOCABN - 1;

    {
        int half = tid >> 9;
        int idx = tid & 511;
        int t = half ? t1 : t0;
        hq[half][idx] = ((const ull*)(g_qA + (size_t)t * 1024))[idx];
    }
    __syncthreads();

    ull a0 = 0ull, a1 = 0ull;
    const float4* wb = g_wH4 + (size_t)(p * 64) * VOCABN + j;
    const ull* q0 = &hq[0][p * 128];
    const ull* q1 = &hq[1][p * 128];
#pragma unroll 4
    for (int n = 0; n < 64; n++) {
        float4 w = __ldg(wb + (size_t)n * VOCABN);
        ull w01 = *(const ull*)&w.x;
        ull w23 = *(const ull*)&w.z;
        ull2 qa = *(const ull2*)(q0 + 2 * n);
        ull2 qb = *(const ull2*)(q1 + 2 * n);
        fma2(a0, w01, qa.x); fma2(a0, w23, qa.y);
        fma2(a1, w01, qb.x); fma2(a1, w23, qb.y);
    }
    if (p) {
        redh[0][(p - 1) * 256 + j] = a0;
        redh[1][(p - 1) * 256 + j] = a1;
    }

    // j == 256 column: 1024-way K split, k = tid
    {
        float w256 = ((const float*)&g_wH4[(size_t)(tid >> 2) * VOCABN + 256])[tid & 3];
        float s0 = w256 * ((const float*)hq[0])[tid];
        float s1 = w256 * ((const float*)hq[1])[tid];
#pragma unroll
        for (int off = 16; off; off >>= 1) {
            s0 += __shfl_down_sync(0xFFFFFFFFu, s0, off);
            s1 += __shfl_down_sync(0xFFFFFFFFu, s1, off);
        }
        if ((tid & 31) == 0) {
            redj[0][tid >> 5] = s0;
            redj[1][tid >> 5] = s1;
        }
    }
    __syncthreads();

    if (p == 0) {
#pragma unroll
        for (int s = 0; s < 3; s++) {
            a0 = add2(a0, redh[0][s * 256 + j]);
            a1 = add2(a1, redh[1][s * 256 + j]);
        }
        float2 r0 = unpack2(a0), r1 = unpack2(a1);
        g_logits[(size_t)t0 * VOCABN + j] = r0.x + r0.y;
        g_logits[(size_t)t1 * VOCABN + j] = r1.x + r1.y;
    }
    if (tid == 0) {
        float s0 = 0.f, s1 = 0.f;
#pragma unroll
        for (int w = 0; w < 32; w++) { s0 += redj[0][w]; s1 += redj[1][w]; }
        g_logits[(size_t)t0 * VOCABN + 256] = s0;
        g_logits[(size_t)t1 * VOCABN + 256] = s1;
    }
}

// ---------------- K5: gather logits to output ----------------
__global__ void k_gather(const int* __restrict__ x, float* __restrict__ out) {
    int warp = threadIdx.x >> 5, lane = threadIdx.x & 31;
    int pp = blockIdx.x * 8 + warp;
    int tok = x[pp];
    const float* row = g_logits + (size_t)tok * VOCABN;
    float* orow = out + (size_t)pp * VOCABN;
    for (int v = lane; v < VOCABN; v += 32)
        orow[v] = row[v];
}

// ---------------- K6: stability loss (2-stage) ----------------
__global__ void k_loss1(const int* __restrict__ x) {
    __shared__ float red[256];
    int tid = threadIdx.x;
    int base = blockIdx.x * 512;
    red[tid] = g_L[x[base + tid]] + g_L[x[base + 256 + tid]];
    __syncthreads();
    for (int k = 128; k > 0; k >>= 1) {
        if (tid < k) red[tid] += red[tid + k];
        __syncthreads();
    }
    if (tid == 0) g_part[blockIdx.x] = red[0];
}
__global__ void k_loss2(float* __restrict__ out, int out_size) {
    __shared__ float w2[2];
    int tid = threadIdx.x;
    float s = g_part[tid];
#pragma unroll
    for (int off = 16; off; off >>= 1)
        s += __shfl_down_sync(0xFFFFFFFFu, s, off);
    if ((tid & 31) == 0) w2[tid >> 5] = s;
    __syncthreads();
    if (tid == 0 && out_size > BSV)
        out[BSV] = (w2[0] + w2[1]) * (1.0f / NPOS);
}

// ---------------- launch ----------------
extern "C" void kernel_launch(void* const* d_in, const int* in_sizes, int n_in,
                              void* d_out, int out_size) {
    (void)in_sizes; (void)n_in;
    const int*   x   = (const int*)d_in[0];
    const float* emb = (const float*)d_in[1];
    const float* e0  = (const float*)d_in[2];
    const float* e1  = (const float*)d_in[3];
    const float* e2  = (const float*)d_in[4];
    const float* e3  = (const float*)d_in[5];
    const float* e4  = (const float*)d_in[6];
    const float* e5  = (const float*)d_in[7];
    const float* e6  = (const float*)d_in[8];
    const float* e7  = (const float*)d_in[9];
    const float* wl  = (const float*)d_in[10];
    const float* wh  = (const float*)d_in[11];
    float* out = (float*)d_out;

    k_prep_layers<<<192, 256>>>(wl);
    k_prep_head<<<72, 256>>>(wh);
    k_expand<<<VOCABN, 128>>>(emb, e0, e1, e2, e3, e4, e5, e6, e7);
    for (int d = 0; d < DEPTHN; d++)
        k_layer<<<(VOCABN + 1) / 2, 1024>>>(d, d & 1);
    k_L<<<VOCABN, 256>>>();
    k_head<<<(VOCABN + 1) / 2, 1024>>>();
    k_gather<<<NPOS / 8, 256>>>(x, out);
    k_loss1<<<64, 256>>>(x);
    k_loss2<<<1, 64>>>(out, out_size);
}